// round 14
// baseline (speedup 1.0000x reference)
#include <cuda_runtime.h>
#include <cuda_fp16.h>
#include <cstdint>

#define M_TOTAL 16384
#define KDIM    4096
#define NDIM    4096
#define NKT     64           // KDIM / 64
#define RANK    16
#define STAGES  3
#define STAGE_BYTES 32768    // A tile 16KB + B tile 16KB
#define CTRL    1024
#define SMEM_MAIN (1024 + CTRL + STAGES * STAGE_BYTES)
#define LCHUNK  512          // k-chunk staged in smem for lora phase

static constexpr int CONV_TPB = 256;

// -------- static device scratch (no cudaMalloc allowed) --------
__device__ __align__(16) __half g_xs[(size_t)M_TOTAL * KDIM]; // 128 MB tiled+swizzled
__device__ __align__(16) __half g_ws[(size_t)NDIM * KDIM];    //  32 MB tiled+swizzled
__device__ float g_inter[(size_t)M_TOTAL * RANK];

// ---------------- PTX helpers (sm_100-baseline only; NO tcgen05) ----------------
__device__ __forceinline__ uint32_t s2u(const void* p) {
    return (uint32_t)__cvta_generic_to_shared(p);
}
__device__ __forceinline__ void mbar_init(uint32_t a, uint32_t cnt) {
    asm volatile("mbarrier.init.shared.b64 [%0], %1;" :: "r"(a), "r"(cnt) : "memory");
}
__device__ __forceinline__ void mbar_arrive(uint32_t a) {
    asm volatile("mbarrier.arrive.shared.b64 _, [%0];" :: "r"(a) : "memory");
}
__device__ __forceinline__ void mbar_expect_tx(uint32_t a, uint32_t bytes) {
    asm volatile("mbarrier.arrive.expect_tx.shared.b64 _, [%0], %1;"
                 :: "r"(a), "r"(bytes) : "memory");
}
__device__ __forceinline__ void mbar_wait(uint32_t a, uint32_t parity) {
    asm volatile("{\n\t.reg .pred P;\n"
        "W_%=:\n\t"
        "mbarrier.try_wait.parity.acquire.cta.shared::cta.b64 P, [%0], %1;\n\t"
        "@!P bra W_%=;\n\t}" :: "r"(a), "r"(parity) : "memory");
}
__device__ __forceinline__ void bulk_cp16k(uint32_t dst, const void* src, uint32_t mbar) {
    asm volatile(
        "cp.async.bulk.shared::cluster.global.mbarrier::complete_tx::bytes "
        "[%0], [%1], %2, [%3];"
        :: "r"(dst), "l"(src), "r"(16384u), "r"(mbar) : "memory");
}
__device__ __forceinline__ void ldsm4(uint32_t* d, uint32_t addr) {
    asm volatile("ldmatrix.sync.aligned.m8n8.x4.shared.b16 {%0,%1,%2,%3}, [%4];"
        : "=r"(d[0]), "=r"(d[1]), "=r"(d[2]), "=r"(d[3]) : "r"(addr));
}
__device__ __forceinline__ void mma16816(float* c, const uint32_t* a, const uint32_t* b) {
    asm volatile("mma.sync.aligned.m16n8k16.row.col.f32.f16.f16.f32 "
        "{%0,%1,%2,%3}, {%4,%5,%6,%7}, {%8,%9}, {%0,%1,%2,%3};"
        : "+f"(c[0]), "+f"(c[1]), "+f"(c[2]), "+f"(c[3])
        : "r"(a[0]), "r"(a[1]), "r"(a[2]), "r"(a[3]), "r"(b[0]), "r"(b[1]));
}
__device__ __forceinline__ uint32_t sw128(uint32_t o) { return o ^ ((o >> 3) & 0x70); }

// ---------------- fused: fp32 x -> tiled fp16  AND  lora inter ----------------
// block = 512 threads handles 8 rows of x. Phase 1 converts rows (warms L2);
// phase 2 computes inter = x . A[slot] with A staged through padded smem as
// fp16 (halves the LDS crossbar traffic) and half2 FMA.
__global__ void __launch_bounds__(512) conv_lora_kernel(
    const float* __restrict__ x,
    const float* __restrict__ loraA,
    const int* __restrict__ lidx)
{
    __shared__ __half As[LCHUNK][40];  // padded: 80B row stride -> conflict-free
    __shared__ float sm[16][16];
    int m0 = blockIdx.x * 8;
    int tid = threadIdx.x;

    // ---- phase 1: convert 8 rows to tiled/swizzled fp16 ----
#pragma unroll
    for (int it = 0; it < 8; it++) {
        int m = m0 + it;
        int k = tid * 8;
        const float4* src = reinterpret_cast<const float4*>(x + (size_t)m * KDIM + k);
        float4 v0 = src[0], v1 = src[1];
        __half o[8] = {__float2half_rn(v0.x), __float2half_rn(v0.y),
                       __float2half_rn(v0.z), __float2half_rn(v0.w),
                       __float2half_rn(v1.x), __float2half_rn(v1.y),
                       __float2half_rn(v1.z), __float2half_rn(v1.w)};
        int tile_m = m >> 7, r = m & 127, kt = k >> 6, c = k & 63;
        uint32_t off = sw128((uint32_t)(r * 128 + c * 2));
        char* dst = reinterpret_cast<char*>(g_xs)
                    + ((size_t)(tile_m * NKT + kt)) * 16384 + off;
        *reinterpret_cast<uint4*>(dst) = *reinterpret_cast<uint4*>(o);
    }

    // ---- phase 2: inter[m][r] = x[m,:] . A[slot][:,r] ----
    int slot = lidx[m0 >> 11];
    int i = tid >> 6;
    int j = tid & 63;
    const float* xr = x + (size_t)(m0 + i) * KDIM;
    const float* A = loraA + (size_t)slot * KDIM * RANK;
    __half2 acc2[8];
#pragma unroll
    for (int p = 0; p < 8; p++) acc2[p] = __float2half2_rn(0.f);

    for (int cb = 0; cb < KDIM; cb += LCHUNK) {
        __syncthreads();
        const float4* Ac = reinterpret_cast<const float4*>(A + (size_t)cb * RANK);
#pragma unroll
        for (int t = 0; t < 4; t++) {
            int idx = tid + t * 512;
            int kk = idx >> 2, q = idx & 3;
            float4 v = Ac[idx];
            union { __half2 h[2]; unsigned long long ull; } u;
            u.h[0] = __floats2half2_rn(v.x, v.y);
            u.h[1] = __floats2half2_rn(v.z, v.w);
            *reinterpret_cast<unsigned long long*>(&As[kk][q * 4]) = u.ull;
        }
        __syncthreads();
#pragma unroll
        for (int t = 0; t < LCHUNK / 64; t++) {
            int kl = j + t * 64;
            __half2 xv2 = __float2half2_rn(xr[cb + kl]);
            uint4 r0 = *reinterpret_cast<const uint4*>(&As[kl][0]);
            uint4 r1 = *reinterpret_cast<const uint4*>(&As[kl][8]);
            acc2[0] = __hfma2(*reinterpret_cast<__half2*>(&r0.x), xv2, acc2[0]);
            acc2[1] = __hfma2(*reinterpret_cast<__half2*>(&r0.y), xv2, acc2[1]);
            acc2[2] = __hfma2(*reinterpret_cast<__half2*>(&r0.z), xv2, acc2[2]);
            acc2[3] = __hfma2(*reinterpret_cast<__half2*>(&r0.w), xv2, acc2[3]);
            acc2[4] = __hfma2(*reinterpret_cast<__half2*>(&r1.x), xv2, acc2[4]);
            acc2[5] = __hfma2(*reinterpret_cast<__half2*>(&r1.y), xv2, acc2[5]);
            acc2[6] = __hfma2(*reinterpret_cast<__half2*>(&r1.z), xv2, acc2[6]);
            acc2[7] = __hfma2(*reinterpret_cast<__half2*>(&r1.w), xv2, acc2[7]);
        }
    }
    float acc[16];
#pragma unroll
    for (int p = 0; p < 8; p++) {
        float2 f = __half22float2(acc2[p]);
        acc[2 * p] = f.x; acc[2 * p + 1] = f.y;
    }
#pragma unroll
    for (int r = 0; r < 16; r++)
#pragma unroll
        for (int off = 16; off; off >>= 1)
            acc[r] += __shfl_xor_sync(0xffffffff, acc[r], off);
    int wrp = tid >> 5;
    if ((tid & 31) == 0)
#pragma unroll
        for (int r = 0; r < 16; r++) sm[wrp][r] = acc[r];
    __syncthreads();
    if (tid < 128) {
        int ii = tid >> 4, r = tid & 15;
        g_inter[(size_t)(m0 + ii) * RANK + r] = sm[ii * 2][r] + sm[ii * 2 + 1][r];
    }
}

// ---------------- convert weights: fp32 -> tiled, swizzled fp16 ----------------
__global__ void conv_w_kernel(const float* __restrict__ w) {
    const int CH = KDIM / 8;
    long gid = (long)blockIdx.x * CONV_TPB + threadIdx.x;
    int n  = (int)(gid / CH);
    int c8 = (int)(gid % CH);
    if (n >= NDIM) return;
    int k = c8 * 8;
    const float4* src = reinterpret_cast<const float4*>(w + (size_t)n * KDIM + k);
    float4 v0 = src[0], v1 = src[1];
    __half o[8] = {__float2half_rn(v0.x), __float2half_rn(v0.y),
                   __float2half_rn(v0.z), __float2half_rn(v0.w),
                   __float2half_rn(v1.x), __float2half_rn(v1.y),
                   __float2half_rn(v1.z), __float2half_rn(v1.w)};
    int tile_n = n >> 7, r = n & 127, kt = k >> 6, c = k & 63;
    uint32_t off = sw128((uint32_t)(r * 128 + c * 2));
    char* dst = reinterpret_cast<char*>(g_ws) + ((size_t)(tile_n * NKT + kt)) * 16384 + off;
    *reinterpret_cast<uint4*>(dst) = *reinterpret_cast<uint4*>(o);
}

// ---------------- main GEMM: 128x128 tile, mma.sync fp16, 3-stage pipeline ----------------
// Producer duty ROTATES across warps (wid == kt&7): the empty-wait stalls only
// 1/8 warps per kt instead of serializing warp 0 on the whole CTA every kt.
__global__ void __launch_bounds__(256, 2) gemm_kernel(
    const float* __restrict__ bias,
    const float* __restrict__ loraB,
    const int* __restrict__ lidx,
    float* __restrict__ out)
{
    extern __shared__ char smem_raw[];
    char* smem = (char*)(((uintptr_t)smem_raw + 1023) & ~(uintptr_t)1023);
    uint32_t sbase = s2u(smem);
    int tid = threadIdx.x;
    int wid = tid >> 5;
    int lane = tid & 31;
    int wm = wid & 1;          // 2 warp rows  (64 M each)
    int wn = wid >> 1;         // 4 warp cols  (32 N each)

    // CTA swizzle: groups of 8 bm x 32 bn share tiles in L2
    int grp = blockIdx.x >> 8, rem = blockIdx.x & 255;
    int bm = (grp << 3) | (rem & 7);   // [0,128)
    int bn = rem >> 3;                 // [0,32)

    // barriers: full[s]@8+16s, empty[s]@16+16s
    uint32_t mb_full0 = sbase + 8;
    if (tid == 0) {
        for (int s = 0; s < STAGES; s++) {
            mbar_init(mb_full0 + s * 16, 1);       // full: tx-based
            mbar_init(mb_full0 + s * 16 + 8, 8);   // empty: 8 warp arrivals
        }
        asm volatile("fence.proxy.async.shared::cta;" ::: "memory");
    }
    __syncthreads();

    const char* xs = reinterpret_cast<const char*>(g_xs);
    const char* ws = reinterpret_cast<const char*>(g_ws);
    const char* aTiles = xs + ((size_t)bm * NKT) * 16384;
    const char* bTiles = ws + ((size_t)bn * NKT) * 16384;

    // prologue: fill all stages
    if (tid == 0) {
#pragma unroll
        for (int s = 0; s < STAGES; s++) {
            uint32_t full = mb_full0 + s * 16;
            mbar_expect_tx(full, STAGE_BYTES);
            uint32_t dst = sbase + CTRL + s * STAGE_BYTES;
            bulk_cp16k(dst,         aTiles + (size_t)s * 16384, full);
            bulk_cp16k(dst + 16384, bTiles + (size_t)s * 16384, full);
        }
    }

    // per-lane ldmatrix address components (SW128 pre-swizzled tiles)
    int g = lane >> 3, rin = lane & 7;
    int a_row = wm * 64 + (g & 1) * 8 + rin;
    int a_khalf = g >> 1;
    uint32_t a_base = (uint32_t)(a_row << 7);
    uint32_t a_sw = (uint32_t)(rin << 4);
    int b_row = wn * 32 + (g >> 1) * 8 + rin;
    int b_kadd = g & 1;
    uint32_t b_base = (uint32_t)(b_row << 7);
    uint32_t b_sw = (uint32_t)(rin << 4);

    float c[4][4][4];
#pragma unroll
    for (int i = 0; i < 4; i++)
#pragma unroll
        for (int j = 0; j < 4; j++)
#pragma unroll
            for (int q = 0; q < 4; q++) c[i][j][q] = 0.f;

    int s = 0, ph = 0;   // stage/phase induction (no div/mod)
#pragma unroll 1
    for (int kt = 0; kt < NKT; kt++) {
        mbar_wait(mb_full0 + s * 16, ph);
        uint32_t sA = sbase + CTRL + s * STAGE_BYTES;
        uint32_t sB = sA + 16384;
#pragma unroll
        for (int ks = 0; ks < 4; ks++) {
            uint32_t a[4][4], b[4][2];
#pragma unroll
            for (int i = 0; i < 4; i++) {
                uint32_t addr = sA + a_base + (uint32_t)(i * 2048)
                              + ((((uint32_t)(ks * 2 + a_khalf)) << 4) ^ a_sw);
                ldsm4(a[i], addr);
            }
#pragma unroll
            for (int jp = 0; jp < 2; jp++) {
                uint32_t r4[4];
                uint32_t addr = sB + b_base + (uint32_t)(jp * 2048)
                              + ((((uint32_t)(ks * 2 + b_kadd)) << 4) ^ b_sw);
                ldsm4(r4, addr);
                b[jp * 2][0] = r4[0]; b[jp * 2][1] = r4[1];
                b[jp * 2 + 1][0] = r4[2]; b[jp * 2 + 1][1] = r4[3];
            }
            // release stage smem as soon as its last ldmatrix retired
            if (ks == 3 && lane == 0) mbar_arrive(mb_full0 + s * 16 + 8);
#pragma unroll
            for (int i = 0; i < 4; i++)
#pragma unroll
                for (int j = 0; j < 4; j++)
                    mma16816(c[i][j], a[i], b[j]);
        }
        // rotating producer: warp (kt&7) refills stage s for iteration kt+STAGES
        if (wid == (kt & 7) && lane == 0 && kt + STAGES < NKT) {
            mbar_wait(mb_full0 + s * 16 + 8, ph);           // all 8 warps released
            uint32_t full = mb_full0 + s * 16;
            mbar_expect_tx(full, STAGE_BYTES);
            uint32_t dst = sbase + CTRL + s * STAGE_BYTES;
            bulk_cp16k(dst,         aTiles + (size_t)(kt + STAGES) * 16384, full);
            bulk_cp16k(dst + 16384, bTiles + (size_t)(kt + STAGES) * 16384, full);
        }
        if (++s == STAGES) { s = 0; ph ^= 1; }
    }
    __syncthreads();

    // ---- fused epilogue: bias + LoRA from register accumulators ----
    float* loraB_s = reinterpret_cast<float*>(smem + CTRL);        // [16][128]
    float* bias_s  = loraB_s + 16 * 128;                           // [128]
    int n0 = bn * 128;
    int slot = lidx[bm >> 4];
    if (tid < 128) bias_s[tid] = bias[n0 + tid];
    for (int idx = tid; idx < 16 * 128; idx += 256) {
        int r = idx >> 7, nn = idx & 127;
        loraB_s[idx] = loraB[((size_t)slot * 16 + r) * NDIM + n0 + nn];
    }
    __syncthreads();

#pragma unroll
    for (int i = 0; i < 4; i++) {
#pragma unroll
        for (int h = 0; h < 2; h++) {
            int m = bm * 128 + wm * 64 + i * 16 + h * 8 + (lane >> 2);
            float it[16];
            const float4* ip = reinterpret_cast<const float4*>(g_inter + (size_t)m * RANK);
#pragma unroll
            for (int q = 0; q < 4; q++) {
                float4 t = ip[q];
                it[q * 4 + 0] = t.x; it[q * 4 + 1] = t.y;
                it[q * 4 + 2] = t.z; it[q * 4 + 3] = t.w;
            }
#pragma unroll
            for (int j = 0; j < 4; j++) {
                int nn = wn * 32 + j * 8 + 2 * (lane & 3);
                float acc0 = bias_s[nn], acc1 = bias_s[nn + 1];
#pragma unroll
                for (int r = 0; r < 16; r++) {
                    acc0 += it[r] * loraB_s[r * 128 + nn];
                    acc1 += it[r] * loraB_s[r * 128 + nn + 1];
                }
                float2 v;
                v.x = c[i][j][h * 2 + 0] + acc0;
                v.y = c[i][j][h * 2 + 1] + acc1;
                *reinterpret_cast<float2*>(out + (size_t)m * NDIM + n0 + nn) = v;
            }
        }
    }
}

// ---------------- launch ----------------
extern "C" void kernel_launch(void* const* d_in, const int* in_sizes, int n_in,
                              void* d_out, int out_size) {
    const float* x    = (const float*)d_in[0];
    const float* w    = (const float*)d_in[1];
    const float* bias = (const float*)d_in[2];
    const float* lA   = (const float*)d_in[3];
    const float* lB   = (const float*)d_in[4];
    const int*   lidx = (const int*)d_in[5];
    float* out = (float*)d_out;

    cudaFuncSetAttribute(gemm_kernel,
                         cudaFuncAttributeMaxDynamicSharedMemorySize, SMEM_MAIN);

    conv_w_kernel<<<(NDIM * (KDIM / 8)) / CONV_TPB, CONV_TPB>>>(w);
    conv_lora_kernel<<<M_TOTAL / 8, 512>>>(x, lA, lidx);
    gemm_kernel<<<4096, 256, SMEM_MAIN>>>(bias, lB, lidx, out);
}

// round 15
// speedup vs baseline: 1.0117x; 1.0117x over previous
#include <cuda_runtime.h>
#include <cuda_fp16.h>
#include <cstdint>

#define M_TOTAL 16384
#define KDIM    4096
#define NDIM    4096
#define NKT     64           // KDIM / 64
#define RANK    16
#define STAGES  3
#define STAGE_BYTES 32768    // A tile 16KB + B tile 16KB
#define CTRL    1024
#define SMEM_MAIN (1024 + CTRL + STAGES * STAGE_BYTES)
#define LCHUNK  512          // k-chunk staged in smem for lora phase
#define LORA_BLOCKS (M_TOTAL / 8)          // 2048
#define CONVW_BLOCKS ((NDIM * (KDIM / 8)) / 512)   // 4096

// -------- static device scratch (no cudaMalloc allowed) --------
__device__ __align__(16) __half g_xs[(size_t)M_TOTAL * KDIM]; // 128 MB tiled+swizzled
__device__ __align__(16) __half g_ws[(size_t)NDIM * KDIM];    //  32 MB tiled+swizzled
__device__ float g_inter[(size_t)M_TOTAL * RANK];

// ---------------- PTX helpers (sm_100-baseline only; NO tcgen05) ----------------
__device__ __forceinline__ uint32_t s2u(const void* p) {
    return (uint32_t)__cvta_generic_to_shared(p);
}
__device__ __forceinline__ void mbar_init(uint32_t a, uint32_t cnt) {
    asm volatile("mbarrier.init.shared.b64 [%0], %1;" :: "r"(a), "r"(cnt) : "memory");
}
__device__ __forceinline__ void mbar_arrive(uint32_t a) {
    asm volatile("mbarrier.arrive.shared.b64 _, [%0];" :: "r"(a) : "memory");
}
__device__ __forceinline__ void mbar_expect_tx(uint32_t a, uint32_t bytes) {
    asm volatile("mbarrier.arrive.expect_tx.shared.b64 _, [%0], %1;"
                 :: "r"(a), "r"(bytes) : "memory");
}
__device__ __forceinline__ void mbar_wait(uint32_t a, uint32_t parity) {
    asm volatile("{\n\t.reg .pred P;\n"
        "W_%=:\n\t"
        "mbarrier.try_wait.parity.acquire.cta.shared::cta.b64 P, [%0], %1;\n\t"
        "@!P bra W_%=;\n\t}" :: "r"(a), "r"(parity) : "memory");
}
__device__ __forceinline__ void bulk_cp16k(uint32_t dst, const void* src, uint32_t mbar) {
    asm volatile(
        "cp.async.bulk.shared::cluster.global.mbarrier::complete_tx::bytes "
        "[%0], [%1], %2, [%3];"
        :: "r"(dst), "l"(src), "r"(16384u), "r"(mbar) : "memory");
}
__device__ __forceinline__ void ldsm4(uint32_t* d, uint32_t addr) {
    asm volatile("ldmatrix.sync.aligned.m8n8.x4.shared.b16 {%0,%1,%2,%3}, [%4];"
        : "=r"(d[0]), "=r"(d[1]), "=r"(d[2]), "=r"(d[3]) : "r"(addr));
}
__device__ __forceinline__ void mma16816(float* c, const uint32_t* a, const uint32_t* b) {
    asm volatile("mma.sync.aligned.m16n8k16.row.col.f32.f16.f16.f32 "
        "{%0,%1,%2,%3}, {%4,%5,%6,%7}, {%8,%9}, {%0,%1,%2,%3};"
        : "+f"(c[0]), "+f"(c[1]), "+f"(c[2]), "+f"(c[3])
        : "r"(a[0]), "r"(a[1]), "r"(a[2]), "r"(a[3]), "r"(b[0]), "r"(b[1]));
}
__device__ __forceinline__ uint32_t sw128(uint32_t o) { return o ^ ((o >> 3) & 0x70); }

// ---------------- merged preproc: lora blocks [0,2048) + w-convert blocks [2048,6144) ----
// lora path: 512 threads handle 8 rows of x. Phase 1 converts rows (warms L2);
// phase 2 computes inter = x . A[slot] with fp16-staged A in padded smem.
// w path:   512 threads convert 512*8 w elements into tiled/swizzled fp16.
__global__ void __launch_bounds__(512) preproc_kernel(
    const float* __restrict__ x,
    const float* __restrict__ w,
    const float* __restrict__ loraA,
    const int* __restrict__ lidx)
{
    __shared__ __half As[LCHUNK][40];  // padded: 80B row stride -> conflict-free
    __shared__ float sm[16][16];
    int tid = threadIdx.x;

    if (blockIdx.x >= LORA_BLOCKS) {
        // ---- w-convert path ----
        int bid = blockIdx.x - LORA_BLOCKS;
        const int CH = KDIM / 8;
        long gid = (long)bid * 512 + tid;
        int n  = (int)(gid / CH);
        int c8 = (int)(gid % CH);
        int k = c8 * 8;
        const float4* src = reinterpret_cast<const float4*>(w + (size_t)n * KDIM + k);
        float4 v0 = src[0], v1 = src[1];
        __half o[8] = {__float2half_rn(v0.x), __float2half_rn(v0.y),
                       __float2half_rn(v0.z), __float2half_rn(v0.w),
                       __float2half_rn(v1.x), __float2half_rn(v1.y),
                       __float2half_rn(v1.z), __float2half_rn(v1.w)};
        int tile_n = n >> 7, r = n & 127, kt = k >> 6, c = k & 63;
        uint32_t off = sw128((uint32_t)(r * 128 + c * 2));
        char* dst = reinterpret_cast<char*>(g_ws)
                    + ((size_t)(tile_n * NKT + kt)) * 16384 + off;
        *reinterpret_cast<uint4*>(dst) = *reinterpret_cast<uint4*>(o);
        return;
    }

    // ---- lora path ----
    int m0 = blockIdx.x * 8;

    // phase 1: convert 8 rows of x to tiled/swizzled fp16
#pragma unroll
    for (int it = 0; it < 8; it++) {
        int m = m0 + it;
        int k = tid * 8;
        const float4* src = reinterpret_cast<const float4*>(x + (size_t)m * KDIM + k);
        float4 v0 = src[0], v1 = src[1];
        __half o[8] = {__float2half_rn(v0.x), __float2half_rn(v0.y),
                       __float2half_rn(v0.z), __float2half_rn(v0.w),
                       __float2half_rn(v1.x), __float2half_rn(v1.y),
                       __float2half_rn(v1.z), __float2half_rn(v1.w)};
        int tile_m = m >> 7, r = m & 127, kt = k >> 6, c = k & 63;
        uint32_t off = sw128((uint32_t)(r * 128 + c * 2));
        char* dst = reinterpret_cast<char*>(g_xs)
                    + ((size_t)(tile_m * NKT + kt)) * 16384 + off;
        *reinterpret_cast<uint4*>(dst) = *reinterpret_cast<uint4*>(o);
    }

    // phase 2: inter[m][r] = x[m,:] . A[slot][:,r]
    int slot = lidx[m0 >> 11];
    int i = tid >> 6;
    int j = tid & 63;
    const float* xr = x + (size_t)(m0 + i) * KDIM;
    const float* A = loraA + (size_t)slot * KDIM * RANK;
    __half2 acc2[8];
#pragma unroll
    for (int p = 0; p < 8; p++) acc2[p] = __float2half2_rn(0.f);

    for (int cb = 0; cb < KDIM; cb += LCHUNK) {
        __syncthreads();
        const float4* Ac = reinterpret_cast<const float4*>(A + (size_t)cb * RANK);
#pragma unroll
        for (int t = 0; t < 4; t++) {
            int idx = tid + t * 512;
            int kk = idx >> 2, q = idx & 3;
            float4 v = Ac[idx];
            union { __half2 h[2]; unsigned long long ull; } u;
            u.h[0] = __floats2half2_rn(v.x, v.y);
            u.h[1] = __floats2half2_rn(v.z, v.w);
            *reinterpret_cast<unsigned long long*>(&As[kk][q * 4]) = u.ull;
        }
        __syncthreads();
#pragma unroll
        for (int t = 0; t < LCHUNK / 64; t++) {
            int kl = j + t * 64;
            __half2 xv2 = __float2half2_rn(xr[cb + kl]);
            uint4 r0 = *reinterpret_cast<const uint4*>(&As[kl][0]);
            uint4 r1 = *reinterpret_cast<const uint4*>(&As[kl][8]);
            acc2[0] = __hfma2(*reinterpret_cast<__half2*>(&r0.x), xv2, acc2[0]);
            acc2[1] = __hfma2(*reinterpret_cast<__half2*>(&r0.y), xv2, acc2[1]);
            acc2[2] = __hfma2(*reinterpret_cast<__half2*>(&r0.z), xv2, acc2[2]);
            acc2[3] = __hfma2(*reinterpret_cast<__half2*>(&r0.w), xv2, acc2[3]);
            acc2[4] = __hfma2(*reinterpret_cast<__half2*>(&r1.x), xv2, acc2[4]);
            acc2[5] = __hfma2(*reinterpret_cast<__half2*>(&r1.y), xv2, acc2[5]);
            acc2[6] = __hfma2(*reinterpret_cast<__half2*>(&r1.z), xv2, acc2[6]);
            acc2[7] = __hfma2(*reinterpret_cast<__half2*>(&r1.w), xv2, acc2[7]);
        }
    }
    float acc[16];
#pragma unroll
    for (int p = 0; p < 8; p++) {
        float2 f = __half22float2(acc2[p]);
        acc[2 * p] = f.x; acc[2 * p + 1] = f.y;
    }
#pragma unroll
    for (int r = 0; r < 16; r++)
#pragma unroll
        for (int off = 16; off; off >>= 1)
            acc[r] += __shfl_xor_sync(0xffffffff, acc[r], off);
    int wrp = tid >> 5;
    if ((tid & 31) == 0)
#pragma unroll
        for (int r = 0; r < 16; r++) sm[wrp][r] = acc[r];
    __syncthreads();
    if (tid < 128) {
        int ii = tid >> 4, r = tid & 15;
        g_inter[(size_t)(m0 + ii) * RANK + r] = sm[ii * 2][r] + sm[ii * 2 + 1][r];
    }
}

// ---------------- main GEMM: 128x128 tile, mma.sync fp16, 3-stage pipeline ----------------
__global__ void __launch_bounds__(256, 2) gemm_kernel(
    const float* __restrict__ bias,
    const float* __restrict__ loraB,
    const int* __restrict__ lidx,
    float* __restrict__ out)
{
    extern __shared__ char smem_raw[];
    char* smem = (char*)(((uintptr_t)smem_raw + 1023) & ~(uintptr_t)1023);
    uint32_t sbase = s2u(smem);
    int tid = threadIdx.x;
    int wid = tid >> 5;
    int lane = tid & 31;
    int wm = wid & 1;          // 2 warp rows  (64 M each)
    int wn = wid >> 1;         // 4 warp cols  (32 N each)

    // CTA swizzle: groups of 8 bm x 32 bn share tiles in L2
    int grp = blockIdx.x >> 8, rem = blockIdx.x & 255;
    int bm = (grp << 3) | (rem & 7);   // [0,128)
    int bn = rem >> 3;                 // [0,32)

    // barriers: full[s]@8+16s, empty[s]@16+16s
    uint32_t mb_full0 = sbase + 8;
    if (tid == 0) {
        for (int s = 0; s < STAGES; s++) {
            mbar_init(mb_full0 + s * 16, 1);       // full: tx-based
            mbar_init(mb_full0 + s * 16 + 8, 8);   // empty: 8 warp arrivals
        }
        asm volatile("fence.proxy.async.shared::cta;" ::: "memory");
    }
    __syncthreads();

    const char* xs = reinterpret_cast<const char*>(g_xs);
    const char* ws = reinterpret_cast<const char*>(g_ws);
    const char* aTiles = xs + ((size_t)bm * NKT) * 16384;
    const char* bTiles = ws + ((size_t)bn * NKT) * 16384;

    // prologue: fill all stages
    if (tid == 0) {
#pragma unroll
        for (int s = 0; s < STAGES; s++) {
            uint32_t full = mb_full0 + s * 16;
            mbar_expect_tx(full, STAGE_BYTES);
            uint32_t dst = sbase + CTRL + s * STAGE_BYTES;
            bulk_cp16k(dst,         aTiles + (size_t)s * 16384, full);
            bulk_cp16k(dst + 16384, bTiles + (size_t)s * 16384, full);
        }
    }

    // per-lane ldmatrix address components (SW128 pre-swizzled tiles)
    int g = lane >> 3, rin = lane & 7;
    int a_row = wm * 64 + (g & 1) * 8 + rin;
    int a_khalf = g >> 1;
    uint32_t a_base = (uint32_t)(a_row << 7);
    uint32_t a_sw = (uint32_t)(rin << 4);
    int b_row = wn * 32 + (g >> 1) * 8 + rin;
    int b_kadd = g & 1;
    uint32_t b_base = (uint32_t)(b_row << 7);
    uint32_t b_sw = (uint32_t)(rin << 4);

    float c[4][4][4];
#pragma unroll
    for (int i = 0; i < 4; i++)
#pragma unroll
        for (int j = 0; j < 4; j++)
#pragma unroll
            for (int q = 0; q < 4; q++) c[i][j][q] = 0.f;

    int s = 0, ph = 0;   // stage/phase induction (no div/mod)
#pragma unroll 1
    for (int kt = 0; kt < NKT; kt++) {
        mbar_wait(mb_full0 + s * 16, ph);
        uint32_t sA = sbase + CTRL + s * STAGE_BYTES;
        uint32_t sB = sA + 16384;
#pragma unroll
        for (int ks = 0; ks < 4; ks++) {
            uint32_t a[4][4], b[4][2];
#pragma unroll
            for (int i = 0; i < 4; i++) {
                uint32_t addr = sA + a_base + (uint32_t)(i * 2048)
                              + ((((uint32_t)(ks * 2 + a_khalf)) << 4) ^ a_sw);
                ldsm4(a[i], addr);
            }
#pragma unroll
            for (int jp = 0; jp < 2; jp++) {
                uint32_t r4[4];
                uint32_t addr = sB + b_base + (uint32_t)(jp * 2048)
                              + ((((uint32_t)(ks * 2 + b_kadd)) << 4) ^ b_sw);
                ldsm4(r4, addr);
                b[jp * 2][0] = r4[0]; b[jp * 2][1] = r4[1];
                b[jp * 2 + 1][0] = r4[2]; b[jp * 2 + 1][1] = r4[3];
            }
            // release stage smem as soon as its last ldmatrix retired
            if (ks == 3 && lane == 0) mbar_arrive(mb_full0 + s * 16 + 8);
#pragma unroll
            for (int i = 0; i < 4; i++)
#pragma unroll
                for (int j = 0; j < 4; j++)
                    mma16816(c[i][j], a[i], b[j]);
        }
        if (tid == 0 && kt + STAGES < NKT) {
            mbar_wait(mb_full0 + s * 16 + 8, ph);           // all 8 warps released
            uint32_t full = mb_full0 + s * 16;
            mbar_expect_tx(full, STAGE_BYTES);
            uint32_t dst = sbase + CTRL + s * STAGE_BYTES;
            bulk_cp16k(dst,         aTiles + (size_t)(kt + STAGES) * 16384, full);
            bulk_cp16k(dst + 16384, bTiles + (size_t)(kt + STAGES) * 16384, full);
        }
        if (++s == STAGES) { s = 0; ph ^= 1; }
    }
    __syncthreads();

    // ---- fused epilogue: bias + LoRA from register accumulators ----
    float* loraB_s = reinterpret_cast<float*>(smem + CTRL);        // [16][128]
    float* bias_s  = loraB_s + 16 * 128;                           // [128]
    int n0 = bn * 128;
    int slot = lidx[bm >> 4];
    if (tid < 128) bias_s[tid] = bias[n0 + tid];
    for (int idx = tid; idx < 16 * 128; idx += 256) {
        int r = idx >> 7, nn = idx & 127;
        loraB_s[idx] = loraB[((size_t)slot * 16 + r) * NDIM + n0 + nn];
    }
    __syncthreads();

#pragma unroll
    for (int i = 0; i < 4; i++) {
#pragma unroll
        for (int h = 0; h < 2; h++) {
            int m = bm * 128 + wm * 64 + i * 16 + h * 8 + (lane >> 2);
            float it[16];
            const float4* ip = reinterpret_cast<const float4*>(g_inter + (size_t)m * RANK);
#pragma unroll
            for (int q = 0; q < 4; q++) {
                float4 t = ip[q];
                it[q * 4 + 0] = t.x; it[q * 4 + 1] = t.y;
                it[q * 4 + 2] = t.z; it[q * 4 + 3] = t.w;
            }
#pragma unroll
            for (int j = 0; j < 4; j++) {
                int nn = wn * 32 + j * 8 + 2 * (lane & 3);
                float acc0 = bias_s[nn], acc1 = bias_s[nn + 1];
#pragma unroll
                for (int r = 0; r < 16; r++) {
                    acc0 += it[r] * loraB_s[r * 128 + nn];
                    acc1 += it[r] * loraB_s[r * 128 + nn + 1];
                }
                float2 v;
                v.x = c[i][j][h * 2 + 0] + acc0;
                v.y = c[i][j][h * 2 + 1] + acc1;
                *reinterpret_cast<float2*>(out + (size_t)m * NDIM + n0 + nn) = v;
            }
        }
    }
}

// ---------------- launch ----------------
extern "C" void kernel_launch(void* const* d_in, const int* in_sizes, int n_in,
                              void* d_out, int out_size) {
    const float* x    = (const float*)d_in[0];
    const float* w    = (const float*)d_in[1];
    const float* bias = (const float*)d_in[2];
    const float* lA   = (const float*)d_in[3];
    const float* lB   = (const float*)d_in[4];
    const int*   lidx = (const int*)d_in[5];
    float* out = (float*)d_out;

    cudaFuncSetAttribute(gemm_kernel,
                         cudaFuncAttributeMaxDynamicSharedMemorySize, SMEM_MAIN);

    preproc_kernel<<<LORA_BLOCKS + CONVW_BLOCKS, 512>>>(x, w, lA, lidx);
    gemm_kernel<<<4096, 256, SMEM_MAIN>>>(bias, lB, lidx, out);
}

// round 16
// speedup vs baseline: 1.0178x; 1.0059x over previous
#include <cuda_runtime.h>
#include <cuda_fp16.h>
#include <cstdint>

#define M_TOTAL 16384
#define KDIM    4096
#define NDIM    4096
#define NKT     64           // KDIM / 64
#define RANK    16
#define STAGES  3
#define STAGE_BYTES 32768    // A tile 16KB + B tile 16KB
#define CTRL    1024
#define EPI_OFF (CTRL + STAGES * STAGE_BYTES)   // dedicated epilogue region
#define EPI_BYTES 8704                          // inter 8KB + bias 512B
#define SMEM_MAIN (1024 + EPI_OFF + EPI_BYTES)
#define LCHUNK  512          // k-chunk staged in smem for lora phase
#define LORA_BLOCKS (M_TOTAL / 8)                  // 2048
#define CONVW_BLOCKS ((NDIM * (KDIM / 8)) / 512)   // 4096

// -------- static device scratch (no cudaMalloc allowed) --------
__device__ __align__(16) __half g_xs[(size_t)M_TOTAL * KDIM]; // 128 MB tiled+swizzled
__device__ __align__(16) __half g_ws[(size_t)NDIM * KDIM];    //  32 MB tiled+swizzled
__device__ __align__(16) float g_inter[(size_t)M_TOTAL * RANK];

// ---------------- PTX helpers (sm_100-baseline only; NO tcgen05) ----------------
__device__ __forceinline__ uint32_t s2u(const void* p) {
    return (uint32_t)__cvta_generic_to_shared(p);
}
__device__ __forceinline__ void mbar_init(uint32_t a, uint32_t cnt) {
    asm volatile("mbarrier.init.shared.b64 [%0], %1;" :: "r"(a), "r"(cnt) : "memory");
}
__device__ __forceinline__ void mbar_arrive(uint32_t a) {
    asm volatile("mbarrier.arrive.shared.b64 _, [%0];" :: "r"(a) : "memory");
}
__device__ __forceinline__ void mbar_expect_tx(uint32_t a, uint32_t bytes) {
    asm volatile("mbarrier.arrive.expect_tx.shared.b64 _, [%0], %1;"
                 :: "r"(a), "r"(bytes) : "memory");
}
__device__ __forceinline__ void mbar_wait(uint32_t a, uint32_t parity) {
    asm volatile("{\n\t.reg .pred P;\n"
        "W_%=:\n\t"
        "mbarrier.try_wait.parity.acquire.cta.shared::cta.b64 P, [%0], %1;\n\t"
        "@!P bra W_%=;\n\t}" :: "r"(a), "r"(parity) : "memory");
}
__device__ __forceinline__ void bulk_cp(uint32_t dst, const void* src, uint32_t bytes,
                                        uint32_t mbar) {
    asm volatile(
        "cp.async.bulk.shared::cluster.global.mbarrier::complete_tx::bytes "
        "[%0], [%1], %2, [%3];"
        :: "r"(dst), "l"(src), "r"(bytes), "r"(mbar) : "memory");
}
__device__ __forceinline__ void ldsm4(uint32_t* d, uint32_t addr) {
    asm volatile("ldmatrix.sync.aligned.m8n8.x4.shared.b16 {%0,%1,%2,%3}, [%4];"
        : "=r"(d[0]), "=r"(d[1]), "=r"(d[2]), "=r"(d[3]) : "r"(addr));
}
__device__ __forceinline__ void mma16816(float* c, const uint32_t* a, const uint32_t* b) {
    asm volatile("mma.sync.aligned.m16n8k16.row.col.f32.f16.f16.f32 "
        "{%0,%1,%2,%3}, {%4,%5,%6,%7}, {%8,%9}, {%0,%1,%2,%3};"
        : "+f"(c[0]), "+f"(c[1]), "+f"(c[2]), "+f"(c[3])
        : "r"(a[0]), "r"(a[1]), "r"(a[2]), "r"(a[3]), "r"(b[0]), "r"(b[1]));
}
__device__ __forceinline__ uint32_t sw128(uint32_t o) { return o ^ ((o >> 3) & 0x70); }

// ---------------- merged preproc: lora blocks [0,2048) + w-convert blocks [2048,6144) ----
__global__ void __launch_bounds__(512) preproc_kernel(
    const float* __restrict__ x,
    const float* __restrict__ w,
    const float* __restrict__ loraA,
    const int* __restrict__ lidx)
{
    __shared__ __half As[LCHUNK][40];  // padded: 80B row stride -> conflict-free
    __shared__ float sm[16][16];
    int tid = threadIdx.x;

    if (blockIdx.x >= LORA_BLOCKS) {
        // ---- w-convert path ----
        int bid = blockIdx.x - LORA_BLOCKS;
        const int CH = KDIM / 8;
        long gid = (long)bid * 512 + tid;
        int n  = (int)(gid / CH);
        int c8 = (int)(gid % CH);
        int k = c8 * 8;
        const float4* src = reinterpret_cast<const float4*>(w + (size_t)n * KDIM + k);
        float4 v0 = src[0], v1 = src[1];
        __half o[8] = {__float2half_rn(v0.x), __float2half_rn(v0.y),
                       __float2half_rn(v0.z), __float2half_rn(v0.w),
                       __float2half_rn(v1.x), __float2half_rn(v1.y),
                       __float2half_rn(v1.z), __float2half_rn(v1.w)};
        int tile_n = n >> 7, r = n & 127, kt = k >> 6, c = k & 63;
        uint32_t off = sw128((uint32_t)(r * 128 + c * 2));
        char* dst = reinterpret_cast<char*>(g_ws)
                    + ((size_t)(tile_n * NKT + kt)) * 16384 + off;
        *reinterpret_cast<uint4*>(dst) = *reinterpret_cast<uint4*>(o);
        return;
    }

    // ---- lora path ----
    int m0 = blockIdx.x * 8;

    // phase 1: convert 8 rows of x to tiled/swizzled fp16
#pragma unroll
    for (int it = 0; it < 8; it++) {
        int m = m0 + it;
        int k = tid * 8;
        const float4* src = reinterpret_cast<const float4*>(x + (size_t)m * KDIM + k);
        float4 v0 = src[0], v1 = src[1];
        __half o[8] = {__float2half_rn(v0.x), __float2half_rn(v0.y),
                       __float2half_rn(v0.z), __float2half_rn(v0.w),
                       __float2half_rn(v1.x), __float2half_rn(v1.y),
                       __float2half_rn(v1.z), __float2half_rn(v1.w)};
        int tile_m = m >> 7, r = m & 127, kt = k >> 6, c = k & 63;
        uint32_t off = sw128((uint32_t)(r * 128 + c * 2));
        char* dst = reinterpret_cast<char*>(g_xs)
                    + ((size_t)(tile_m * NKT + kt)) * 16384 + off;
        *reinterpret_cast<uint4*>(dst) = *reinterpret_cast<uint4*>(o);
    }

    // phase 2: inter[m][r] = x[m,:] . A[slot][:,r]
    int slot = lidx[m0 >> 11];
    int i = tid >> 6;
    int j = tid & 63;
    const float* xr = x + (size_t)(m0 + i) * KDIM;
    const float* A = loraA + (size_t)slot * KDIM * RANK;
    __half2 acc2[8];
#pragma unroll
    for (int p = 0; p < 8; p++) acc2[p] = __float2half2_rn(0.f);

    for (int cb = 0; cb < KDIM; cb += LCHUNK) {
        __syncthreads();
        const float4* Ac = reinterpret_cast<const float4*>(A + (size_t)cb * RANK);
#pragma unroll
        for (int t = 0; t < 4; t++) {
            int idx = tid + t * 512;
            int kk = idx >> 2, q = idx & 3;
            float4 v = Ac[idx];
            union { __half2 h[2]; unsigned long long ull; } u;
            u.h[0] = __floats2half2_rn(v.x, v.y);
            u.h[1] = __floats2half2_rn(v.z, v.w);
            *reinterpret_cast<unsigned long long*>(&As[kk][q * 4]) = u.ull;
        }
        __syncthreads();
#pragma unroll
        for (int t = 0; t < LCHUNK / 64; t++) {
            int kl = j + t * 64;
            __half2 xv2 = __float2half2_rn(xr[cb + kl]);
            uint4 r0 = *reinterpret_cast<const uint4*>(&As[kl][0]);
            uint4 r1 = *reinterpret_cast<const uint4*>(&As[kl][8]);
            acc2[0] = __hfma2(*reinterpret_cast<__half2*>(&r0.x), xv2, acc2[0]);
            acc2[1] = __hfma2(*reinterpret_cast<__half2*>(&r0.y), xv2, acc2[1]);
            acc2[2] = __hfma2(*reinterpret_cast<__half2*>(&r0.z), xv2, acc2[2]);
            acc2[3] = __hfma2(*reinterpret_cast<__half2*>(&r0.w), xv2, acc2[3]);
            acc2[4] = __hfma2(*reinterpret_cast<__half2*>(&r1.x), xv2, acc2[4]);
            acc2[5] = __hfma2(*reinterpret_cast<__half2*>(&r1.y), xv2, acc2[5]);
            acc2[6] = __hfma2(*reinterpret_cast<__half2*>(&r1.z), xv2, acc2[6]);
            acc2[7] = __hfma2(*reinterpret_cast<__half2*>(&r1.w), xv2, acc2[7]);
        }
    }
    float acc[16];
#pragma unroll
    for (int p = 0; p < 8; p++) {
        float2 f = __half22float2(acc2[p]);
        acc[2 * p] = f.x; acc[2 * p + 1] = f.y;
    }
#pragma unroll
    for (int r = 0; r < 16; r++)
#pragma unroll
        for (int off = 16; off; off >>= 1)
            acc[r] += __shfl_xor_sync(0xffffffff, acc[r], off);
    int wrp = tid >> 5;
    if ((tid & 31) == 0)
#pragma unroll
        for (int r = 0; r < 16; r++) sm[wrp][r] = acc[r];
    __syncthreads();
    if (tid < 128) {
        int ii = tid >> 4, r = tid & 15;
        g_inter[(size_t)(m0 + ii) * RANK + r] = sm[ii * 2][r] + sm[ii * 2 + 1][r];
    }
}

// ---------------- main GEMM: 128x128 tile, mma.sync fp16, 3-stage pipeline ----------------
// Epilogue operands (inter slice + bias slice) are prefetched into a dedicated
// smem region via cp.async.bulk at CTA start, fully overlapped with the mainloop.
__global__ void __launch_bounds__(256, 2) gemm_kernel(
    const float* __restrict__ bias,
    const float* __restrict__ loraB,
    const int* __restrict__ lidx,
    float* __restrict__ out)
{
    extern __shared__ char smem_raw[];
    char* smem = (char*)(((uintptr_t)smem_raw + 1023) & ~(uintptr_t)1023);
    uint32_t sbase = s2u(smem);
    int tid = threadIdx.x;
    int wid = tid >> 5;
    int lane = tid & 31;
    int wm = wid & 1;          // 2 warp rows  (64 M each)
    int wn = wid >> 1;         // 4 warp cols  (32 N each)

    // CTA swizzle: groups of 8 bm x 32 bn share tiles in L2
    int grp = blockIdx.x >> 8, rem = blockIdx.x & 255;
    int bm = (grp << 3) | (rem & 7);   // [0,128)
    int bn = rem >> 3;                 // [0,32)
    int n0 = bn * 128;

    // barriers: full[s]@8+16s, empty[s]@16+16s, epilogue@64
    uint32_t mb_full0 = sbase + 8;
    uint32_t mb_epi = sbase + 64;
    if (tid == 0) {
        for (int s = 0; s < STAGES; s++) {
            mbar_init(mb_full0 + s * 16, 1);       // full: tx-based
            mbar_init(mb_full0 + s * 16 + 8, 8);   // empty: 8 warp arrivals
        }
        mbar_init(mb_epi, 1);
        asm volatile("fence.proxy.async.shared::cta;" ::: "memory");
    }
    __syncthreads();

    const char* xs = reinterpret_cast<const char*>(g_xs);
    const char* ws = reinterpret_cast<const char*>(g_ws);
    const char* aTiles = xs + ((size_t)bm * NKT) * 16384;
    const char* bTiles = ws + ((size_t)bn * NKT) * 16384;

    // prologue: epilogue-operand prefetch + fill all stages
    if (tid == 0) {
        mbar_expect_tx(mb_epi, EPI_BYTES);
        bulk_cp(sbase + EPI_OFF, g_inter + (size_t)bm * 128 * RANK, 8192, mb_epi);
        bulk_cp(sbase + EPI_OFF + 8192, bias + n0, 512, mb_epi);
#pragma unroll
        for (int s = 0; s < STAGES; s++) {
            uint32_t full = mb_full0 + s * 16;
            mbar_expect_tx(full, STAGE_BYTES);
            uint32_t dst = sbase + CTRL + s * STAGE_BYTES;
            bulk_cp(dst,         aTiles + (size_t)s * 16384, 16384, full);
            bulk_cp(dst + 16384, bTiles + (size_t)s * 16384, 16384, full);
        }
    }

    // per-lane ldmatrix address components (SW128 pre-swizzled tiles)
    int g = lane >> 3, rin = lane & 7;
    int a_row = wm * 64 + (g & 1) * 8 + rin;
    int a_khalf = g >> 1;
    uint32_t a_base = (uint32_t)(a_row << 7);
    uint32_t a_sw = (uint32_t)(rin << 4);
    int b_row = wn * 32 + (g >> 1) * 8 + rin;
    int b_kadd = g & 1;
    uint32_t b_base = (uint32_t)(b_row << 7);
    uint32_t b_sw = (uint32_t)(rin << 4);

    float c[4][4][4];
#pragma unroll
    for (int i = 0; i < 4; i++)
#pragma unroll
        for (int j = 0; j < 4; j++)
#pragma unroll
            for (int q = 0; q < 4; q++) c[i][j][q] = 0.f;

    int s = 0, ph = 0;   // stage/phase induction (no div/mod)
#pragma unroll 1
    for (int kt = 0; kt < NKT; kt++) {
        mbar_wait(mb_full0 + s * 16, ph);
        uint32_t sA = sbase + CTRL + s * STAGE_BYTES;
        uint32_t sB = sA + 16384;
#pragma unroll
        for (int ks = 0; ks < 4; ks++) {
            uint32_t a[4][4], b[4][2];
#pragma unroll
            for (int i = 0; i < 4; i++) {
                uint32_t addr = sA + a_base + (uint32_t)(i * 2048)
                              + ((((uint32_t)(ks * 2 + a_khalf)) << 4) ^ a_sw);
                ldsm4(a[i], addr);
            }
#pragma unroll
            for (int jp = 0; jp < 2; jp++) {
                uint32_t r4[4];
                uint32_t addr = sB + b_base + (uint32_t)(jp * 2048)
                              + ((((uint32_t)(ks * 2 + b_kadd)) << 4) ^ b_sw);
                ldsm4(r4, addr);
                b[jp * 2][0] = r4[0]; b[jp * 2][1] = r4[1];
                b[jp * 2 + 1][0] = r4[2]; b[jp * 2 + 1][1] = r4[3];
            }
            // release stage smem as soon as its last ldmatrix retired
            if (ks == 3 && lane == 0) mbar_arrive(mb_full0 + s * 16 + 8);
#pragma unroll
            for (int i = 0; i < 4; i++)
#pragma unroll
                for (int j = 0; j < 4; j++)
                    mma16816(c[i][j], a[i], b[j]);
        }
        if (tid == 0 && kt + STAGES < NKT) {
            mbar_wait(mb_full0 + s * 16 + 8, ph);           // all 8 warps released
            uint32_t full = mb_full0 + s * 16;
            mbar_expect_tx(full, STAGE_BYTES);
            uint32_t dst = sbase + CTRL + s * STAGE_BYTES;
            bulk_cp(dst,         aTiles + (size_t)(kt + STAGES) * 16384, 16384, full);
            bulk_cp(dst + 16384, bTiles + (size_t)(kt + STAGES) * 16384, 16384, full);
        }
        if (++s == STAGES) { s = 0; ph ^= 1; }
    }
    __syncthreads();

    // ---- fused epilogue: bias + LoRA; inter/bias from prefetched smem ----
    float* loraB_s = reinterpret_cast<float*>(smem + CTRL);        // [16][128] (stage area, now dead)
    const float* inter_s = reinterpret_cast<const float*>(smem + EPI_OFF);      // [128][16]
    const float* bias_s  = reinterpret_cast<const float*>(smem + EPI_OFF + 8192); // [128]
    int slot = lidx[bm >> 4];
    mbar_wait(mb_epi, 0);
    for (int idx = tid; idx < 16 * 128; idx += 256) {
        int r = idx >> 7, nn = idx & 127;
        loraB_s[idx] = loraB[((size_t)slot * 16 + r) * NDIM + n0 + nn];
    }
    __syncthreads();

#pragma unroll
    for (int i = 0; i < 4; i++) {
#pragma unroll
        for (int h = 0; h < 2; h++) {
            int m_local = wm * 64 + i * 16 + h * 8 + (lane >> 2);
            int m = bm * 128 + m_local;
            float it[16];
            const float4* ip = reinterpret_cast<const float4*>(inter_s + m_local * RANK);
#pragma unroll
            for (int q = 0; q < 4; q++) {
                float4 t = ip[q];
                it[q * 4 + 0] = t.x; it[q * 4 + 1] = t.y;
                it[q * 4 + 2] = t.z; it[q * 4 + 3] = t.w;
            }
#pragma unroll
            for (int j = 0; j < 4; j++) {
                int nn = wn * 32 + j * 8 + 2 * (lane & 3);
                float acc0 = bias_s[nn], acc1 = bias_s[nn + 1];
#pragma unroll
                for (int r = 0; r < 16; r++) {
                    acc0 += it[r] * loraB_s[r * 128 + nn];
                    acc1 += it[r] * loraB_s[r * 128 + nn + 1];
                }
                float2 v;
                v.x = c[i][j][h * 2 + 0] + acc0;
                v.y = c[i][j][h * 2 + 1] + acc1;
                *reinterpret_cast<float2*>(out + (size_t)m * NDIM + n0 + nn) = v;
            }
        }
    }
}

// ---------------- launch ----------------
extern "C" void kernel_launch(void* const* d_in, const int* in_sizes, int n_in,
                              void* d_out, int out_size) {
    const float* x    = (const float*)d_in[0];
    const float* w    = (const float*)d_in[1];
    const float* bias = (const float*)d_in[2];
    const float* lA   = (const float*)d_in[3];
    const float* lB   = (const float*)d_in[4];
    const int*   lidx = (const int*)d_in[5];
    float* out = (float*)d_out;

    cudaFuncSetAttribute(gemm_kernel,
                         cudaFuncAttributeMaxDynamicSharedMemorySize, SMEM_MAIN);

    preproc_kernel<<<LORA_BLOCKS + CONVW_BLOCKS, 512>>>(x, w, lA, lidx);
    gemm_kernel<<<4096, 256, SMEM_MAIN>>>(bias, lB, lidx, out);
}